// round 8
// baseline (speedup 1.0000x reference)
#include <cuda_runtime.h>
#include <math.h>

#define B_DIM 64
#define D_DIM 65536
#define S_SL  8
#define NTH   512
#define SLICE (D_DIM / S_SL)
#define QPT   (SLICE / 4 / NTH)     // 4 quads per thread
#define NTB   1024
#define CAP   2048
#define NB    128
#define KBASE 6128                   // (key>>19) at x = 1.0

// ---- __device__ scratch (allocation-free; self-resetting counters) ----
__device__ unsigned g_cand[B_DIM * D_DIM];        // candidate keys (worst-case cap)
__device__ int      g_cnt[B_DIM];                 // per-row candidate counts
__device__ unsigned g_hist[B_DIM * S_SL * NB];
__device__ float    g_hsum[B_DIM * S_SL * NB];
__device__ float    g_sl_loc[B_DIM * S_SL];
__device__ float    g_sl_bce[B_DIM * S_SL];
__device__ int      g_sl_pos[B_DIM * S_SL];
__device__ float    g_row_loc[B_DIM];
__device__ float    g_row_conf[B_DIM];
__device__ int      g_row_pos[B_DIM];
__device__ int      g_row_sel[B_DIM];
__device__ int      g_ctr;                        // last-CTA counter (self-reset)

__device__ __forceinline__ float softplus_f(float x) {
    return fmaxf(x, 0.0f) + log1pf(expf(-fabsf(x)));
}
__device__ __forceinline__ float sl1f(float d) {
    float ad = fabsf(d);
    return (ad < 1.0f) ? 0.5f * d * d : (ad - 0.5f);
}
__device__ __forceinline__ unsigned key_of(float x) {
    unsigned u = __float_as_uint(x);
    return (u & 0x80000000u) ? ~u : (u | 0x80000000u);
}
__device__ __forceinline__ float val_of_key(unsigned k) {
    unsigned u = (k & 0x80000000u) ? (k & 0x7FFFFFFFu) : ~k;
    return __uint_as_float(u);
}
__device__ __forceinline__ int hot_bin(unsigned key) {      // valid only if x>=1.0
    return min((int)(key >> 19) - KBASE, NB - 1);
}

template<int NWARP>
__device__ __forceinline__ float blk_sum(float v, float* red, int t) {
    #pragma unroll
    for (int o = 16; o > 0; o >>= 1) v += __shfl_down_sync(0xFFFFFFFFu, v, o);
    if ((t & 31) == 0) red[t >> 5] = v;
    __syncthreads();
    if (t < 32) {
        float w = (t < NWARP) ? red[t] : 0.0f;
        #pragma unroll
        for (int o = 16; o > 0; o >>= 1) w += __shfl_down_sync(0xFFFFFFFFu, w, o);
        if (t == 0) red[0] = w;
    }
    __syncthreads();
    float r = red[0];
    __syncthreads();
    return r;
}

template<int NBINS>
__device__ __forceinline__ int warp_select(const unsigned* h, int k, int lane, int* rem_out) {
    const int PER = NBINS / 32;
    int s = 0;
    #pragma unroll
    for (int m = 0; m < PER; m++) s += (int)h[NBINS - 1 - lane * PER - m];
    int inc = s;
    #pragma unroll
    for (int o = 1; o < 32; o <<= 1) {
        int v = __shfl_up_sync(0xFFFFFFFFu, inc, o);
        if (lane >= o) inc += v;
    }
    int pre = inc - s;
    unsigned m = __ballot_sync(0xFFFFFFFFu, (pre < k) && (pre + s >= k));
    int chosen = __ffs(m) - 1;
    int bin = 0, rem = 0;
    if (lane == chosen) {
        int acc = pre, hi = NBINS - 1 - lane * PER;
        #pragma unroll
        for (int b = 0; b < PER; b++) {
            int c = (int)h[hi - b];
            if (acc + c >= k) { bin = hi - b; rem = k - acc; break; }
            acc += c;
        }
    }
    bin = __shfl_sync(0xFFFFFFFFu, bin, chosen);
    rem = __shfl_sync(0xFFFFFFFFu, rem, chosen);
    *rem_out = rem;
    return bin;
}

// ---------- Pass 1: stats + hot-candidate append + gated histogram ----------
__global__ void __launch_bounds__(NTH) mbl_pass1(
    const float4* __restrict__ loc_data,
    const float4* __restrict__ conf4,
    const float4* __restrict__ loc_t,
    const int4*   __restrict__ ct4)
{
    __shared__ unsigned wh[16][NB];
    __shared__ float    ws[16][NB];
    __shared__ float    red[16];

    const int t = threadIdx.x, w = t >> 5, lane = t & 31;
    const int row = blockIdx.x / S_SL, sl = blockIdx.x % S_SL;

    for (int i = t; i < 16 * NB; i += NTH) { ((unsigned*)wh)[i] = 0; ((float*)ws)[i] = 0.0f; }
    __syncthreads();

    const int qr0 = row * (D_DIM / 4) + sl * (SLICE / 4);
    float npos = 0.0f, pb = 0.0f, ls = 0.0f;

    #pragma unroll
    for (int j = 0; j < QPT; j++) {
        int qg = qr0 + t + j * NTH;
        float4 x = conf4[qg];
        int4   c = ct4[qg];
        float xs[4] = {x.x, x.y, x.z, x.w};
        int   cs[4] = {c.x, c.y, c.z, c.w};
        #pragma unroll
        for (int cc = 0; cc < 4; cc++) {
            bool is_pos = cs[cc] > 0;
            bool is_hot = !is_pos && (xs[cc] >= 1.0f);
            unsigned key = key_of(xs[cc]);
            if (is_pos) {
                size_t e = 4 * (size_t)qg + cc;
                npos += 1.0f; pb += softplus_f(-xs[cc]);
                float4 a = loc_data[e], b = loc_t[e];
                ls += sl1f(a.x - b.x) + sl1f(a.y - b.y) + sl1f(a.z - b.z) + sl1f(a.w - b.w);
            } else if (is_hot) {
                int bin = hot_bin(key);
                atomicAdd(&wh[w][bin], 1u);
                atomicAdd(&ws[w][bin], softplus_f(xs[cc]));
            }
            // warp-aggregated candidate append
            unsigned hot = __ballot_sync(0xFFFFFFFFu, is_hot);
            if (hot) {
                int leader = __ffs(hot) - 1;
                unsigned base = 0;
                if (lane == leader) base = (unsigned)atomicAdd(&g_cnt[row], __popc(hot));
                base = __shfl_sync(0xFFFFFFFFu, base, leader);
                if (is_hot) {
                    int rank = __popc(hot & ((1u << lane) - 1u));
                    g_cand[(size_t)row * D_DIM + base + rank] = key;
                }
            }
        }
    }
    __syncthreads();

    if (t < NB) {
        unsigned s = 0;
        #pragma unroll
        for (int m = 0; m < 16; m++) s += wh[m][t];
        g_hist[blockIdx.x * NB + t] = s;
    } else if (t < 2 * NB) {
        int b = t - NB;
        float s = 0.0f;
        #pragma unroll
        for (int m = 0; m < 16; m++) s += ws[m][b];
        g_hsum[blockIdx.x * NB + b] = s;
    }

    float npos_r = blk_sum<16>(npos, red, t);
    float ls_r   = blk_sum<16>(ls,   red, t);
    float pb_r   = blk_sum<16>(pb,   red, t);
    if (t == 0) {
        g_sl_pos[blockIdx.x] = (int)npos_r;
        g_sl_loc[blockIdx.x] = ls_r;
        g_sl_bce[blockIdx.x] = pb_r;
    }
}

// ---------- Pass 2: per-row select via candidate list + last-CTA reduce ----------
__global__ void __launch_bounds__(NTB) mbl_select(
    const float* __restrict__ conf,
    const int*   __restrict__ ct,
    float* __restrict__ out)
{
    __shared__ unsigned h[NB];
    __shared__ float    hs[NB];
    __shared__ unsigned rh[256];
    __shared__ unsigned list[CAP];
    __shared__ float    red[32];
    __shared__ int      sh_ib, sh_rem, sh_nlist, sh_bin2, sh_rem2, sh_tot, sh_last, sh_cgt;
    __shared__ unsigned sh_T;
    __shared__ int      sh_npos, sh_ncand;
    __shared__ float    sh_pb, sh_ls;

    const int t = threadIdx.x;
    const int row = blockIdx.x;

    if (t < NB) {
        unsigned s = 0;
        #pragma unroll
        for (int m = 0; m < S_SL; m++) s += g_hist[(row * S_SL + m) * NB + t];
        h[t] = s;
    } else if (t < 2 * NB) {
        int b = t - NB;
        float s = 0.0f;
        #pragma unroll
        for (int m = 0; m < S_SL; m++) s += g_hsum[(row * S_SL + m) * NB + b];
        hs[b] = s;
    }
    if (t == 0) {
        int np = 0; float pbs = 0.0f, lss = 0.0f;
        #pragma unroll
        for (int m = 0; m < S_SL; m++) {
            np  += g_sl_pos[row * S_SL + m];
            pbs += g_sl_bce[row * S_SL + m];
            lss += g_sl_loc[row * S_SL + m];
        }
        sh_npos = np; sh_pb = pbs; sh_ls = lss;
        sh_ncand = g_cnt[row];
        g_cnt[row] = 0;                      // self-reset for next replay
        sh_nlist = 0; sh_cgt = 0; sh_T = 0xFFFFFFFFu;
    }
    __syncthreads();
    const int npos_row = sh_npos;
    const int k = min(3 * npos_row, D_DIM);
    const int ncand = sh_ncand;

    if (t < 32) {
        int s = 0;
        #pragma unroll
        for (int m = 0; m < 4; m++) s += (int)h[t * 4 + m];
        #pragma unroll
        for (int o = 16; o > 0; o >>= 1) s += __shfl_down_sync(0xFFFFFFFFu, s, o);
        if (t == 0) sh_tot = s;
        __syncwarp();
        int tot = __shfl_sync(0xFFFFFFFFu, sh_tot, 0);
        if (k > 0 && tot >= k) {
            int rem; int ib = warp_select<NB>(h, k, t, &rem);
            if (t == 0) { sh_ib = ib; sh_rem = rem; }
        } else if (t == 0) sh_ib = -1;
    }
    __syncthreads();
    const int ib = sh_ib;
    const bool fast = (k > 0) && (ib >= 0);
    const int nb_cnt = fast ? (int)h[ib] : 0;
    const unsigned* cand = g_cand + (size_t)row * D_DIM;

    float csum = 0.0f;
    unsigned T = 0u; int req = 0;

    if (fast) {
        if (t < NB && t > ib) csum += hs[t];   // strict part from per-bin sp-sums

        if (nb_cnt <= CAP) {
            // gather boundary-bin keys into shared
            for (int p = t; p < ncand; p += NTB) {
                unsigned kk = cand[p];
                if (hot_bin(kk) == ib) list[atomicAdd(&sh_nlist, 1)] = kk;
            }
            __syncthreads();
            const int rem = sh_rem;
            // O(n^2/NT) exact rank pass: T = min{ key : count(> key) < rem }
            for (int p = t; p < nb_cnt; p += NTB) {
                unsigned myk = list[p];
                int cgt = 0;
                for (int q = 0; q < nb_cnt; q++) cgt += (list[q] > myk);
                if (cgt < rem) atomicMin(&sh_T, myk);
            }
            __syncthreads();
            T = sh_T;
            int loc_gt = 0;
            for (int p = t; p < nb_cnt; p += NTB) {
                unsigned kk = list[p];
                if (kk > T) { csum += softplus_f(val_of_key(kk)); loc_gt++; }
            }
            if (loc_gt) atomicAdd(&sh_cgt, loc_gt);
            __syncthreads();
            req = rem - sh_cgt;
        } else {
            // mid fallback: 4-level radix over candidate list within boundary bin
            unsigned prefix = 0u; int rem = sh_rem;
            for (int lvl = 0; lvl < 4; lvl++) {
                if (t < 256) rh[t] = 0;
                __syncthreads();
                for (int p = t; p < ncand; p += NTB) {
                    unsigned kk = cand[p];
                    if (hot_bin(kk) == ib &&
                        (lvl == 0 || (kk >> (32 - 8 * lvl)) == prefix))
                        atomicAdd(&rh[(kk >> (24 - 8 * lvl)) & 255u], 1u);
                }
                __syncthreads();
                if (t < 32) { int r; int b = warp_select<256>(rh, rem, t, &r);
                              if (t == 0) { sh_bin2 = b; sh_rem2 = r; } }
                __syncthreads();
                prefix = (prefix << 8) | (unsigned)sh_bin2;
                rem = sh_rem2;
                __syncthreads();
            }
            T = prefix; req = rem;
            for (int p = t; p < ncand; p += NTB) {
                unsigned kk = cand[p];
                if (hot_bin(kk) == ib && kk > T) csum += softplus_f(val_of_key(kk));
            }
        }
    } else if (k > 0) {
        // full fallback: exact radix over conf/ct (hot mass insufficient — pathological)
        const size_t r0 = (size_t)row * D_DIM;
        unsigned prefix = 0u; int rem = k;
        for (int lvl = 0; lvl < 4; lvl++) {
            if (t < 256) rh[t] = 0;
            __syncthreads();
            for (int j = 0; j < D_DIM / NTB; j++) {
                size_t e = r0 + t + (size_t)j * NTB;
                if (ct[e] <= 0) {
                    unsigned kk = key_of(conf[e]);
                    if (lvl == 0 || (kk >> (32 - 8 * lvl)) == prefix)
                        atomicAdd(&rh[(kk >> (24 - 8 * lvl)) & 255u], 1u);
                }
            }
            __syncthreads();
            if (t < 32) { int r; int b = warp_select<256>(rh, rem, t, &r);
                          if (t == 0) { sh_bin2 = b; sh_rem2 = r; } }
            __syncthreads();
            prefix = (prefix << 8) | (unsigned)sh_bin2;
            rem = sh_rem2;
            __syncthreads();
        }
        T = prefix; req = rem;
        for (int j = 0; j < D_DIM / NTB; j++) {
            size_t e = r0 + t + (size_t)j * NTB;
            if (ct[e] <= 0) {
                float xv = conf[e];
                if (key_of(xv) > T) csum += softplus_f(xv);
            }
        }
    }
    __syncthreads();

    float csum_row = blk_sum<32>(csum, red, t);
    if (t == 0) {
        float tv = (req > 0) ? softplus_f(val_of_key(T)) : 0.0f;
        g_row_conf[row] = sh_pb + csum_row + (float)req * tv;
        g_row_loc[row]  = sh_ls;
        g_row_pos[row]  = npos_row;
        g_row_sel[row]  = npos_row + k;
        __threadfence();
        int v = atomicAdd(&g_ctr, 1);
        sh_last = (v == B_DIM - 1) ? 1 : 0;
        if (sh_last) g_ctr = 0;
    }
    __syncthreads();
    if (!sh_last) return;
    __threadfence();
    __syncthreads();

    if (t < 64) {
        float lc = g_row_loc[t], cf = g_row_conf[t];
        float ps = (float)g_row_pos[t], slv = (float)g_row_sel[t];
        #pragma unroll
        for (int o = 16; o > 0; o >>= 1) {
            lc  += __shfl_down_sync(0xFFFFFFFFu, lc,  o);
            cf  += __shfl_down_sync(0xFFFFFFFFu, cf,  o);
            ps  += __shfl_down_sync(0xFFFFFFFFu, ps,  o);
            slv += __shfl_down_sync(0xFFFFFFFFu, slv, o);
        }
        if ((t & 31) == 0) {
            red[(t >> 5) * 4 + 0] = lc; red[(t >> 5) * 4 + 1] = cf;
            red[(t >> 5) * 4 + 2] = ps; red[(t >> 5) * 4 + 3] = slv;
        }
    }
    __syncthreads();
    if (t == 0) {
        float lc = red[0] + red[4], cf = red[1] + red[5];
        float ps = red[2] + red[6], slv = red[3] + red[7];
        out[0] = lc / (4.0f * ps) / ps;
        out[1] = cf / slv / ps;
    }
}

extern "C" void kernel_launch(void* const* d_in, const int* in_sizes, int n_in,
                              void* d_out, int out_size)
{
    const float4* loc_data  = nullptr;
    const float4* loc_tgt   = nullptr;
    const float*  conf_data = nullptr;
    const int*    conf_tgt  = nullptr;
    for (int i = 0; i < n_in; i++) {
        if (in_sizes[i] == B_DIM * D_DIM * 4) {
            if (!loc_data) loc_data = (const float4*)d_in[i];
            else           loc_tgt  = (const float4*)d_in[i];
        } else {
            if (!conf_data) conf_data = (const float*)d_in[i];
            else            conf_tgt  = (const int*)d_in[i];
        }
    }

    mbl_pass1<<<B_DIM * S_SL, NTH>>>(loc_data, (const float4*)conf_data,
                                     loc_tgt, (const int4*)conf_tgt);
    mbl_select<<<B_DIM, NTB>>>(conf_data, conf_tgt, (float*)d_out);
}

// round 9
// speedup vs baseline: 4.2160x; 4.2160x over previous
#include <cuda_runtime.h>
#include <math.h>

#define B_DIM 64
#define D_DIM 65536
#define S_SL  8
#define NTH   512
#define SLICE (D_DIM / S_SL)
#define QPT   (SLICE / 4 / NTH)     // 4 quads per thread
#define NTB   1024
#define NBIG  8192                  // fine bins: 10 mantissa bits, x in [1, 256)
#define KB13  392192                // key_of(1.0f) >> 13
#define FXS   1048576.0f            // 2^20 fixed-point scale

// ---- __device__ scratch (allocation-free; BSS-zero; select re-zeroes) ----
__device__ unsigned            g_hcnt[B_DIM * NBIG];     // 2MB per-row fine counts
__device__ unsigned long long  g_hsum[B_DIM * NBIG];     // 4MB fixed-point sp sums
__device__ float g_sl_loc[B_DIM * S_SL];
__device__ float g_sl_bce[B_DIM * S_SL];
__device__ int   g_sl_pos[B_DIM * S_SL];
__device__ float g_row_loc[B_DIM];
__device__ float g_row_conf[B_DIM];
__device__ int   g_row_pos[B_DIM];
__device__ int   g_row_sel[B_DIM];
__device__ int   g_ctr;                                  // self-resetting

__device__ __forceinline__ float softplus_f(float x) {
    return fmaxf(x, 0.0f) + log1pf(expf(-fabsf(x)));
}
__device__ __forceinline__ float sl1f(float d) {
    float ad = fabsf(d);
    return (ad < 1.0f) ? 0.5f * d * d : (ad - 0.5f);
}
__device__ __forceinline__ unsigned key_of(float x) {
    unsigned u = __float_as_uint(x);
    return (u & 0x80000000u) ? ~u : (u | 0x80000000u);
}
__device__ __forceinline__ float val_of_key(unsigned k) {
    unsigned u = (k & 0x80000000u) ? (k & 0x7FFFFFFFu) : ~k;
    return __uint_as_float(u);
}

template<int NWARP>
__device__ __forceinline__ float blk_sum(float v, float* red, int t) {
    #pragma unroll
    for (int o = 16; o > 0; o >>= 1) v += __shfl_down_sync(0xFFFFFFFFu, v, o);
    if ((t & 31) == 0) red[t >> 5] = v;
    __syncthreads();
    if (t < 32) {
        float w = (t < NWARP) ? red[t] : 0.0f;
        #pragma unroll
        for (int o = 16; o > 0; o >>= 1) w += __shfl_down_sync(0xFFFFFFFFu, w, o);
        if (t == 0) red[0] = w;
    }
    __syncthreads();
    float r = red[0];
    __syncthreads();
    return r;
}

// Warp-cooperative descending select over a 256-bin shared histogram (fallback only).
__device__ __forceinline__ int warp_select256(const unsigned* h, int k, int lane, int* rem_out) {
    int s = 0;
    #pragma unroll
    for (int m = 0; m < 8; m++) s += (int)h[255 - lane * 8 - m];
    int inc = s;
    #pragma unroll
    for (int o = 1; o < 32; o <<= 1) {
        int v = __shfl_up_sync(0xFFFFFFFFu, inc, o);
        if (lane >= o) inc += v;
    }
    int pre = inc - s;
    unsigned m = __ballot_sync(0xFFFFFFFFu, (pre < k) && (pre + s >= k));
    int chosen = __ffs(m) - 1;
    int bin = 0, rem = 0;
    if (lane == chosen) {
        int acc = pre, hi = 255 - lane * 8;
        #pragma unroll
        for (int b = 0; b < 8; b++) {
            int c = (int)h[hi - b];
            if (acc + c >= k) { bin = hi - b; rem = k - acc; break; }
            acc += c;
        }
    }
    bin = __shfl_sync(0xFFFFFFFFu, bin, chosen);
    rem = __shfl_sync(0xFFFFFFFFu, rem, chosen);
    *rem_out = rem;
    return bin;
}

// ---------- Pass 1: stats + fine-histogram RED atomics (no shared hist) ----------
__global__ void __launch_bounds__(NTH) mbl_pass1(
    const float4* __restrict__ loc_data,
    const float4* __restrict__ conf4,
    const float4* __restrict__ loc_t,
    const int4*   __restrict__ ct4)
{
    __shared__ float red[16];
    const int t = threadIdx.x;
    const int row = blockIdx.x / S_SL, sl = blockIdx.x % S_SL;
    const int qr0 = row * (D_DIM / 4) + sl * (SLICE / 4);

    unsigned* hc = g_hcnt + (size_t)row * NBIG;
    unsigned long long* hsm = g_hsum + (size_t)row * NBIG;

    float npos = 0.0f, pb = 0.0f, ls = 0.0f;
    #pragma unroll
    for (int j = 0; j < QPT; j++) {
        int qg = qr0 + t + j * NTH;
        float4 x = conf4[qg];
        int4   c = ct4[qg];
        float xs[4] = {x.x, x.y, x.z, x.w};
        int   cs[4] = {c.x, c.y, c.z, c.w};
        #pragma unroll
        for (int cc = 0; cc < 4; cc++) {
            if (cs[cc] > 0) {
                size_t e = 4 * (size_t)qg + cc;
                npos += 1.0f; pb += softplus_f(-xs[cc]);
                float4 a = loc_data[e], b = loc_t[e];
                ls += sl1f(a.x - b.x) + sl1f(a.y - b.y) + sl1f(a.z - b.z) + sl1f(a.w - b.w);
            } else if (xs[cc] >= 1.0f) {
                unsigned key = key_of(xs[cc]);
                int bin = min((int)(key >> 13) - KB13, NBIG - 1);
                float sp = softplus_f(xs[cc]);
                atomicAdd(&hc[bin], 1u);                                 // RED.ADD
                atomicAdd(&hsm[bin], (unsigned long long)(sp * FXS));    // RED.ADD.64
            }
        }
    }

    float npos_r = blk_sum<16>(npos, red, t);
    float ls_r   = blk_sum<16>(ls,   red, t);
    float pb_r   = blk_sum<16>(pb,   red, t);
    if (t == 0) {
        g_sl_pos[blockIdx.x] = (int)npos_r;
        g_sl_loc[blockIdx.x] = ls_r;
        g_sl_bce[blockIdx.x] = pb_r;
    }
}

// ---------- Pass 2: per-row select from fine histogram + last-CTA reduce ----------
__global__ void __launch_bounds__(NTB) mbl_select(
    const float* __restrict__ conf,
    const int*   __restrict__ ct,
    float* __restrict__ out)
{
    __shared__ int      s1[NTB];
    __shared__ int      s2[32];
    __shared__ unsigned rh[256];
    __shared__ float    red[32];
    __shared__ int      sh_npos, sh_k, sh_ib, sh_rem, sh_bin2, sh_rem2, sh_last;
    __shared__ float    sh_pb, sh_ls;

    const int t = threadIdx.x;
    const int row = blockIdx.x;
    const unsigned* hc = g_hcnt + (size_t)row * NBIG;

    if (t == 0) {
        int np = 0; float pbs = 0.0f, lss = 0.0f;
        #pragma unroll
        for (int m = 0; m < S_SL; m++) {
            np  += g_sl_pos[row * S_SL + m];
            pbs += g_sl_bce[row * S_SL + m];
            lss += g_sl_loc[row * S_SL + m];
        }
        sh_npos = np; sh_pb = pbs; sh_ls = lss;
        sh_k = min(3 * np, D_DIM);
    }

    // per-thread sums of 8 consecutive bins (coalesced uint4 pairs)
    {
        const uint4* cp = reinterpret_cast<const uint4*>(hc) + 2 * t;
        uint4 a = cp[0], b = cp[1];
        s1[t] = (int)(a.x + a.y + a.z + a.w + b.x + b.y + b.z + b.w);
    }
    __syncthreads();
    {
        int s = s1[t];
        #pragma unroll
        for (int o = 16; o > 0; o >>= 1) s += __shfl_down_sync(0xFFFFFFFFu, s, o);
        if ((t & 31) == 0) s2[t >> 5] = s;
    }
    __syncthreads();

    if (t == 0) {
        const int k = sh_k;
        int tot = 0;
        #pragma unroll
        for (int w = 0; w < 32; w++) tot += s2[w];
        if (k > 0 && tot >= k) {
            int acc = 0, seg = 0;
            for (int w = 31; w >= 0; w--) {
                if (acc + s2[w] >= k) { seg = w; break; }
                acc += s2[w];
            }
            int ch = seg * 32;
            for (int c = 31; c >= 0; c--) {
                int idx = seg * 32 + c;
                if (acc + s1[idx] >= k) { ch = idx; break; }
                acc += s1[idx];
            }
            int bin = ch * 8;
            for (int b = 7; b >= 0; b--) {
                int idx = ch * 8 + b;
                int cv = (int)hc[idx];
                if (acc + cv >= k) { bin = idx; break; }
                acc += cv;
            }
            sh_ib = bin; sh_rem = k - acc;
        } else sh_ib = -1;
    }
    __syncthreads();
    const int k  = sh_k;
    const int ib = sh_ib;
    const bool fast = (k > 0) && (ib >= 0) && (ib < NBIG - 1);

    // strict-part sum (bins > ib) + zero both arrays for the next replay
    unsigned long long acc64 = 0ull;
    #pragma unroll
    for (int j = 0; j < NBIG / NTB; j++) {           // 8 iterations, coalesced
        int b = t + j * NTB;
        unsigned long long sv = g_hsum[(size_t)row * NBIG + b];
        if (fast && b > ib) acc64 += sv;
        g_hcnt[(size_t)row * NBIG + b] = 0u;
        g_hsum[(size_t)row * NBIG + b] = 0ull;
    }
    float csum = (float)acc64 * (1.0f / FXS);

    unsigned T = 0u; int req = 0;
    if (fast) {
        T = (unsigned)((KB13 + ib) << 13);           // bin lower edge (exact key form)
        req = sh_rem;
    } else if (k > 0) {
        // full fallback: exact 4-level radix select over conf/ct (pathological rows)
        csum = 0.0f;
        const size_t r0 = (size_t)row * D_DIM;
        unsigned prefix = 0u; int rem = k;
        for (int lvl = 0; lvl < 4; lvl++) {
            if (t < 256) rh[t] = 0;
            __syncthreads();
            for (int j = 0; j < D_DIM / NTB; j++) {
                size_t e = r0 + t + (size_t)j * NTB;
                if (ct[e] <= 0) {
                    unsigned kk = key_of(conf[e]);
                    if (lvl == 0 || (kk >> (32 - 8 * lvl)) == prefix)
                        atomicAdd(&rh[(kk >> (24 - 8 * lvl)) & 255u], 1u);
                }
            }
            __syncthreads();
            if (t < 32) { int r; int b = warp_select256(rh, rem, t, &r);
                          if (t == 0) { sh_bin2 = b; sh_rem2 = r; } }
            __syncthreads();
            prefix = (prefix << 8) | (unsigned)sh_bin2;
            rem = sh_rem2;
            __syncthreads();
        }
        T = prefix; req = rem;
        for (int j = 0; j < D_DIM / NTB; j++) {
            size_t e = r0 + t + (size_t)j * NTB;
            if (ct[e] <= 0) {
                float xv = conf[e];
                if (key_of(xv) > T) csum += softplus_f(xv);
            }
        }
    }
    __syncthreads();

    float csum_row = blk_sum<32>(csum, red, t);
    if (t == 0) {
        float tv = (req > 0) ? softplus_f(val_of_key(T)) : 0.0f;
        g_row_conf[row] = sh_pb + csum_row + (float)req * tv;
        g_row_loc[row]  = sh_ls;
        g_row_pos[row]  = sh_npos;
        g_row_sel[row]  = sh_npos + k;
        __threadfence();
        int v = atomicAdd(&g_ctr, 1);
        sh_last = (v == B_DIM - 1) ? 1 : 0;
        if (sh_last) g_ctr = 0;
    }
    __syncthreads();
    if (!sh_last) return;
    __threadfence();
    __syncthreads();

    // global finisher: cross-row reduction
    if (t < 64) {
        float lc = g_row_loc[t], cf = g_row_conf[t];
        float ps = (float)g_row_pos[t], slv = (float)g_row_sel[t];
        #pragma unroll
        for (int o = 16; o > 0; o >>= 1) {
            lc  += __shfl_down_sync(0xFFFFFFFFu, lc,  o);
            cf  += __shfl_down_sync(0xFFFFFFFFu, cf,  o);
            ps  += __shfl_down_sync(0xFFFFFFFFu, ps,  o);
            slv += __shfl_down_sync(0xFFFFFFFFu, slv, o);
        }
        if ((t & 31) == 0) {
            red[(t >> 5) * 4 + 0] = lc; red[(t >> 5) * 4 + 1] = cf;
            red[(t >> 5) * 4 + 2] = ps; red[(t >> 5) * 4 + 3] = slv;
        }
    }
    __syncthreads();
    if (t == 0) {
        float lc = red[0] + red[4], cf = red[1] + red[5];
        float ps = red[2] + red[6], slv = red[3] + red[7];
        out[0] = lc / (4.0f * ps) / ps;
        out[1] = cf / slv / ps;
    }
}

extern "C" void kernel_launch(void* const* d_in, const int* in_sizes, int n_in,
                              void* d_out, int out_size)
{
    const float4* loc_data  = nullptr;
    const float4* loc_tgt   = nullptr;
    const float*  conf_data = nullptr;
    const int*    conf_tgt  = nullptr;
    for (int i = 0; i < n_in; i++) {
        if (in_sizes[i] == B_DIM * D_DIM * 4) {
            if (!loc_data) loc_data = (const float4*)d_in[i];
            else           loc_tgt  = (const float4*)d_in[i];
        } else {
            if (!conf_data) conf_data = (const float*)d_in[i];
            else            conf_tgt  = (const int*)d_in[i];
        }
    }

    mbl_pass1<<<B_DIM * S_SL, NTH>>>(loc_data, (const float4*)conf_data,
                                     loc_tgt, (const int4*)conf_tgt);
    mbl_select<<<B_DIM, NTB>>>(conf_data, conf_tgt, (float*)d_out);
}